// round 2
// baseline (speedup 1.0000x reference)
#include <cuda_runtime.h>
#include <cstdint>

// Problem sizes
static constexpr int NTOK = 8192;
static constexpr int DM   = 1024;
static constexpr int NEXP = 8;
static constexpr int RLO  = 16;
static constexpr int KC   = 1152;   // 1024 + 128 lora-combine columns

// Scratch (device globals; no runtime allocation allowed)
__device__ float g_xr[(long)NTOK * KC];    // [ rna(x) | c ]      (rows: token)
__device__ float g_wr[(long)DM * KC];      // [ rna(W_base) | Bt ] (rows: out dim)
__device__ float g_ac[128L * DM];          // ac[j][k] = rna(A[e][k][r]), j=e*16+r
__device__ float g_hall[(long)NTOK * 128]; // h for all experts

// ---------------------------------------------------------------------------
// Helpers
// ---------------------------------------------------------------------------
static __device__ __forceinline__ uint32_t smem_u32(const void* p) {
    uint32_t a;
    asm("{ .reg .u64 t; cvta.to.shared.u64 t, %1; cvt.u32.u64 %0, t; }" : "=r"(a) : "l"(p));
    return a;
}
static __device__ __forceinline__ float rna_tf32(float v) {
    uint32_t o;
    asm("cvt.rna.tf32.f32 %0, %1;" : "=r"(o) : "f"(v));
    return __uint_as_float(o);
}

#define CP_ASYNC16(saddr, gptr) \
    asm volatile("cp.async.cg.shared.global [%0], [%1], 16;" :: "r"(saddr), "l"(gptr))
#define CP_COMMIT() asm volatile("cp.async.commit_group;" ::: "memory")
#define CP_WAIT1()  asm volatile("cp.async.wait_group 1;" ::: "memory")

#define MMA_TF32(d, a, b) \
    asm volatile("mma.sync.aligned.m16n8k8.row.col.f32.tf32.tf32.f32 " \
        "{%0,%1,%2,%3}, {%4,%5,%6,%7}, {%8,%9}, {%0,%1,%2,%3};" \
        : "+f"((d)[0]), "+f"((d)[1]), "+f"((d)[2]), "+f"((d)[3]) \
        : "r"((a)[0]), "r"((a)[1]), "r"((a)[2]), "r"((a)[3]), \
          "r"((b)[0]), "r"((b)[1]))

// ---------------------------------------------------------------------------
// Prep kernels (convert inputs to tf32-rounded fp32 in GEMM-friendly layouts)
// ---------------------------------------------------------------------------
__global__ void prep_x_kernel(const float* __restrict__ x) {
    long i = (long)blockIdx.x * blockDim.x + threadIdx.x;
    if (i >= (long)NTOK * DM) return;
    long n = i >> 10, d = i & 1023;
    g_xr[n * KC + d] = rna_tf32(x[i]);
}
__global__ void prep_w_kernel(const float* __restrict__ Wb) {
    long i = (long)blockIdx.x * blockDim.x + threadIdx.x;
    if (i >= (long)DM * DM) return;
    long n = i >> 10, k = i & 1023;
    g_wr[n * KC + k] = rna_tf32(Wb[i]);
}
// B[e][r][d]  ->  g_wr[d][1024 + e*16+r]
__global__ void prep_b_kernel(const float* __restrict__ B) {
    int i = blockIdx.x * blockDim.x + threadIdx.x;
    if (i >= 128 * DM) return;
    int j = i >> 10, d = i & 1023;               // read coalesced over d
    g_wr[(long)d * KC + 1024 + j] = rna_tf32(B[(long)j * DM + d]);
}
// A[e][d][r] -> g_ac[j][k] = A[e][k][r]
__global__ void prep_a_kernel(const float* __restrict__ A) {
    int i = blockIdx.x * blockDim.x + threadIdx.x;
    if (i >= 128 * DM) return;
    int j = i >> 10, k = i & 1023;
    int e = j >> 4, r = j & 15;
    g_ac[(long)j * DM + k] = rna_tf32(A[((long)e * DM + k) * RLO + r]);
}

// ---------------------------------------------------------------------------
// Gating + lora-combine assembly (fp32, one warp per token)
// Writes c into g_xr columns [1024, 1152)
// ---------------------------------------------------------------------------
__global__ void __launch_bounds__(256) gate_c_kernel(const float* __restrict__ x,
                                                     const float* __restrict__ Wg) {
    int warp = (blockIdx.x * blockDim.x + threadIdx.x) >> 5;
    int lane = threadIdx.x & 31;
    if (warp >= NTOK) return;
    const float* xr = x + (long)warp * DM;

    float acc[NEXP];
#pragma unroll
    for (int e = 0; e < NEXP; e++) acc[e] = 0.f;
    for (int d = lane; d < DM; d += 32) {
        float xv = xr[d];
#pragma unroll
        for (int e = 0; e < NEXP; e++) acc[e] = fmaf(xv, Wg[e * DM + d], acc[e]);
    }
#pragma unroll
    for (int e = 0; e < NEXP; e++)
#pragma unroll
        for (int s = 16; s > 0; s >>= 1) acc[e] += __shfl_xor_sync(0xFFFFFFFFu, acc[e], s);

    // top-2, first-index tie-break (matches jax.lax.top_k)
    float v0 = -1e30f; int e0 = 0;
#pragma unroll
    for (int e = 0; e < NEXP; e++) if (acc[e] > v0) { v0 = acc[e]; e0 = e; }
    float v1 = -1e30f; int e1 = 0;
#pragma unroll
    for (int e = 0; e < NEXP; e++) if (e != e0 && acc[e] > v1) { v1 = acc[e]; e1 = e; }
    float b  = expf(v1 - v0);
    float w0 = 1.f / (1.f + b);
    float w1 = b * w0;

    float* cp = g_xr + (long)warp * KC + 1024;
    for (int i = lane; i < 128; i += 32) cp[i] = 0.f;
    __syncwarp();
    {
        int j = lane >> 4;                 // which of the two selected experts
        int r = lane & 15;
        int e = j ? e1 : e0;
        float w = j ? w1 : w0;
        float h = g_hall[(long)warp * 128 + e * RLO + r];
        cp[e * RLO + r] = rna_tf32(w * h);
    }
}

// ---------------------------------------------------------------------------
// TF32 GEMM: C[m0+128, n0+128] = A[m,:K] * B[n,:K]^T  (+bias)
// 2-stage cp.async pipeline, 128x128x32 tiles, 8 warps, warp tile 64x32.
// ---------------------------------------------------------------------------
static constexpr int LDS_PAD = 36;            // 32 + 4 floats (bank spread)
static constexpr int STAGE_FLOATS = 2 * 128 * LDS_PAD;   // A + B per stage
static constexpr int SMEM_BYTES = 2 * STAGE_FLOATS * 4;  // 73728

template <int BIAS>
__global__ void __launch_bounds__(256, 2)
gemm_tf32(const float* __restrict__ A, long lda,
          const float* __restrict__ Bm, long ldb,
          float* __restrict__ C, long ldc,
          const float* __restrict__ bias, int ktiles) {
    extern __shared__ __align__(16) float smem[];

    const int tid  = threadIdx.x;
    const int wid  = tid >> 5;
    const int lane = tid & 31;
    const int wm   = wid >> 2;        // 0..1  (64-row half)
    const int wn   = wid & 3;         // 0..3  (32-col quarter)
    const int g    = lane >> 2;       // 0..7
    const int t4   = lane & 3;        // 0..3
    const int m0   = blockIdx.x * 128;
    const int n0   = blockIdx.y * 128;

    const uint32_t sbase = smem_u32(smem);
    const float* Ab = A + (long)m0 * lda;
    const float* Bb = Bm + (long)n0 * ldb;

    // cp.async mapping: 1024 16B-chunks per 128x32 tile, 4 per thread
    const int ldrow = (tid * 4) >> 3;       // rows: tid/2
    const int ldq   = (tid * 4) & 7;        // always even chunk pairs -> use c loop
    (void)ldq;

    auto load_stage = [&](int kt, int stg) {
        const uint32_t sa = sbase + (uint32_t)(stg * STAGE_FLOATS) * 4;
        const uint32_t sb = sa + 128 * LDS_PAD * 4;
        const float* Asrc = Ab + (long)kt * 32;
        const float* Bsrc = Bb + (long)kt * 32;
#pragma unroll
        for (int c = 0; c < 4; c++) {
            int idx = c * 256 + tid;
            int row = idx >> 3, q = idx & 7;
            CP_ASYNC16(sa + (uint32_t)(row * LDS_PAD + q * 4) * 4,
                       Asrc + (long)row * lda + q * 4);
            CP_ASYNC16(sb + (uint32_t)(row * LDS_PAD + q * 4) * 4,
                       Bsrc + (long)row * ldb + q * 4);
        }
        CP_COMMIT();
    };
    (void)ldrow;

    float acc[4][4][4];
#pragma unroll
    for (int i = 0; i < 4; i++)
#pragma unroll
        for (int j = 0; j < 4; j++)
#pragma unroll
            for (int r = 0; r < 4; r++) acc[i][j][r] = 0.f;

    load_stage(0, 0);

    for (int kt = 0; kt < ktiles; kt++) {
        if (kt + 1 < ktiles) load_stage(kt + 1, (kt + 1) & 1);
        else CP_COMMIT();
        CP_WAIT1();
        __syncthreads();

        const int stg = kt & 1;
        const uint32_t* sAu = (const uint32_t*)(smem + stg * STAGE_FLOATS);
        const uint32_t* sBu = sAu + 128 * LDS_PAD;

#pragma unroll
        for (int ks = 0; ks < 4; ks++) {
            const int ko = ks * 8 + t4;
            uint32_t a[4][4];
#pragma unroll
            for (int i = 0; i < 4; i++) {
                int m = wm * 64 + i * 16 + g;
                a[i][0] = sAu[m * LDS_PAD + ko];
                a[i][1] = sAu[(m + 8) * LDS_PAD + ko];
                a[i][2] = sAu[m * LDS_PAD + ko + 4];
                a[i][3] = sAu[(m + 8) * LDS_PAD + ko + 4];
            }
            uint32_t b[4][2];
#pragma unroll
            for (int j = 0; j < 4; j++) {
                int n = wn * 32 + j * 8 + g;
                b[j][0] = sBu[n * LDS_PAD + ko];
                b[j][1] = sBu[n * LDS_PAD + ko + 4];
            }
#pragma unroll
            for (int i = 0; i < 4; i++)
#pragma unroll
                for (int j = 0; j < 4; j++)
                    MMA_TF32(acc[i][j], a[i], b[j]);
        }
        __syncthreads();
    }

    // Epilogue
#pragma unroll
    for (int i = 0; i < 4; i++) {
        int row0 = m0 + wm * 64 + i * 16 + g;
#pragma unroll
        for (int j = 0; j < 4; j++) {
            int col = n0 + wn * 32 + j * 8 + 2 * t4;
            float bx = 0.f, by = 0.f;
            if (BIAS) { bx = bias[col]; by = bias[col + 1]; }
            float2 v0 = { acc[i][j][0] + bx, acc[i][j][1] + by };
            float2 v1 = { acc[i][j][2] + bx, acc[i][j][3] + by };
            *(float2*)(C + (long)row0 * ldc + col)       = v0;
            *(float2*)(C + (long)(row0 + 8) * ldc + col) = v1;
        }
    }
}

// ---------------------------------------------------------------------------
// Launch
// ---------------------------------------------------------------------------
extern "C" void kernel_launch(void* const* d_in, const int* in_sizes, int n_in,
                              void* d_out, int out_size) {
    const float* x    = (const float*)d_in[0];
    const float* Wg   = (const float*)d_in[1];
    const float* A    = (const float*)d_in[2];
    const float* B    = (const float*)d_in[3];
    const float* Wb   = (const float*)d_in[4];
    const float* bias = (const float*)d_in[5];
    float* out = (float*)d_out;

    static bool attr_done = false;
    if (!attr_done) {
        cudaFuncSetAttribute(gemm_tf32<0>, cudaFuncAttributeMaxDynamicSharedMemorySize, SMEM_BYTES);
        cudaFuncSetAttribute(gemm_tf32<1>, cudaFuncAttributeMaxDynamicSharedMemorySize, SMEM_BYTES);
        attr_done = true;
    }

    // 1) tf32-rounded operand staging
    prep_x_kernel<<<(NTOK * DM + 255) / 256, 256>>>(x);
    prep_w_kernel<<<(DM * DM + 255) / 256, 256>>>(Wb);
    prep_b_kernel<<<(128 * DM + 255) / 256, 256>>>(B);
    prep_a_kernel<<<(128 * DM + 255) / 256, 256>>>(A);

    // 2) h = x @ A  for all experts  (8192 x 128 x 1024)
    float* hall;
    cudaGetSymbolAddress((void**)&hall, g_hall);
    float* xr;
    cudaGetSymbolAddress((void**)&xr, g_xr);
    float* wr;
    cudaGetSymbolAddress((void**)&wr, g_wr);
    float* ac;
    cudaGetSymbolAddress((void**)&ac, g_ac);

    gemm_tf32<0><<<dim3(NTOK / 128, 1), 256, SMEM_BYTES>>>(
        xr, KC, ac, DM, hall, 128, nullptr, DM / 32);

    // 3) gating + combine coefficients into g_xr tail columns
    gate_c_kernel<<<(NTOK * 32) / 256, 256>>>(x, Wg);

    // 4) fused output GEMM: out = [x|c] @ [W|Bt]^T + bias  (8192 x 1024 x 1152)
    gemm_tf32<1><<<dim3(NTOK / 128, DM / 128), 256, SMEM_BYTES>>>(
        xr, KC, wr, KC, out, DM, bias, KC / 32);
}

// round 3
// speedup vs baseline: 1.6443x; 1.6443x over previous
#include <cuda_runtime.h>
#include <cuda_fp16.h>
#include <cstdint>

// Problem sizes
static constexpr int NTOK = 8192;
static constexpr int DM   = 1024;
static constexpr int NEXP = 8;
static constexpr int RLO  = 16;
static constexpr int KC   = 1152;   // 1024 + 128 lora-combine columns

// Scratch (device globals; no runtime allocation allowed)
__device__ __half g_xh[(long)NTOK * KC];    // [ x | c ]        (rows: token)
__device__ __half g_wh[(long)DM * KC];      // [ W_base | B^T ] (rows: out dim)
__device__ __half g_ah[128L * DM];          // ah[j][k] = A[e][k][r], j=e*16+r
__device__ float  g_hall[(long)NTOK * 128]; // h for all experts

// ---------------------------------------------------------------------------
// Helpers
// ---------------------------------------------------------------------------
static __device__ __forceinline__ uint32_t smem_u32(const void* p) {
    uint32_t a;
    asm("{ .reg .u64 t; cvta.to.shared.u64 t, %1; cvt.u32.u64 %0, t; }" : "=r"(a) : "l"(p));
    return a;
}

#define CP_ASYNC16(saddr, gptr) \
    asm volatile("cp.async.cg.shared.global [%0], [%1], 16;" :: "r"(saddr), "l"(gptr))
#define CP_COMMIT() asm volatile("cp.async.commit_group;" ::: "memory")
#define CP_WAIT1()  asm volatile("cp.async.wait_group 1;" ::: "memory")

// m16n8k16 fp16 MMA, fp32 accumulate
#define MMA_F16(d, a, b) \
    asm volatile("mma.sync.aligned.m16n8k16.row.col.f32.f16.f16.f32 " \
        "{%0,%1,%2,%3}, {%4,%5,%6,%7}, {%8,%9}, {%0,%1,%2,%3};" \
        : "+f"((d)[0]), "+f"((d)[1]), "+f"((d)[2]), "+f"((d)[3]) \
        : "r"((a)[0]), "r"((a)[1]), "r"((a)[2]), "r"((a)[3]), \
          "r"((b)[0]), "r"((b)[1]))

// ---------------------------------------------------------------------------
// Prep kernels (convert inputs to fp16 in GEMM-friendly layouts)
// ---------------------------------------------------------------------------
__global__ void prep_x_kernel(const float* __restrict__ x) {
    long i = (long)blockIdx.x * blockDim.x + threadIdx.x;
    if (i >= (long)NTOK * DM) return;
    long n = i >> 10, d = i & 1023;
    g_xh[n * KC + d] = __float2half_rn(x[i]);
}
__global__ void prep_w_kernel(const float* __restrict__ Wb) {
    long i = (long)blockIdx.x * blockDim.x + threadIdx.x;
    if (i >= (long)DM * DM) return;
    long n = i >> 10, k = i & 1023;
    g_wh[n * KC + k] = __float2half_rn(Wb[i]);
}
// B[e][r][d]  ->  g_wh[d][1024 + e*16+r]
__global__ void prep_b_kernel(const float* __restrict__ B) {
    int i = blockIdx.x * blockDim.x + threadIdx.x;
    if (i >= 128 * DM) return;
    int j = i >> 10, d = i & 1023;               // read coalesced over d
    g_wh[(long)d * KC + 1024 + j] = __float2half_rn(B[(long)j * DM + d]);
}
// A[e][d][r] -> g_ah[j][k] = A[e][k][r]
__global__ void prep_a_kernel(const float* __restrict__ A) {
    int i = blockIdx.x * blockDim.x + threadIdx.x;
    if (i >= 128 * DM) return;
    int j = i >> 10, k = i & 1023;
    int e = j >> 4, r = j & 15;
    g_ah[(long)j * DM + k] = __float2half_rn(A[((long)e * DM + k) * RLO + r]);
}

// ---------------------------------------------------------------------------
// Gating + lora-combine assembly (fp32 math, one warp per token)
// Writes c into g_xh columns [1024, 1152)
// ---------------------------------------------------------------------------
__global__ void __launch_bounds__(256) gate_c_kernel(const float* __restrict__ x,
                                                     const float* __restrict__ Wg) {
    int warp = (blockIdx.x * blockDim.x + threadIdx.x) >> 5;
    int lane = threadIdx.x & 31;
    if (warp >= NTOK) return;
    const float* xr = x + (long)warp * DM;

    float acc[NEXP];
#pragma unroll
    for (int e = 0; e < NEXP; e++) acc[e] = 0.f;
    for (int d = lane; d < DM; d += 32) {
        float xv = xr[d];
#pragma unroll
        for (int e = 0; e < NEXP; e++) acc[e] = fmaf(xv, Wg[e * DM + d], acc[e]);
    }
#pragma unroll
    for (int e = 0; e < NEXP; e++)
#pragma unroll
        for (int s = 16; s > 0; s >>= 1) acc[e] += __shfl_xor_sync(0xFFFFFFFFu, acc[e], s);

    // top-2, first-index tie-break (matches jax.lax.top_k)
    float v0 = -1e30f; int e0 = 0;
#pragma unroll
    for (int e = 0; e < NEXP; e++) if (acc[e] > v0) { v0 = acc[e]; e0 = e; }
    float v1 = -1e30f; int e1 = 0;
#pragma unroll
    for (int e = 0; e < NEXP; e++) if (e != e0 && acc[e] > v1) { v1 = acc[e]; e1 = e; }
    float b  = expf(v1 - v0);
    float w0 = 1.f / (1.f + b);
    float w1 = b * w0;

    __half* cp = g_xh + (long)warp * KC + 1024;
    for (int i = lane; i < 128; i += 32) cp[i] = __float2half_rn(0.f);
    __syncwarp();
    {
        int j = lane >> 4;                 // which of the two selected experts
        int r = lane & 15;
        int e = j ? e1 : e0;
        float w = j ? w1 : w0;
        float h = g_hall[(long)warp * 128 + e * RLO + r];
        cp[e * RLO + r] = __float2half_rn(w * h);
    }
}

// ---------------------------------------------------------------------------
// FP16 GEMM: C[m0+128, n0+128] = A[m,:K] * B[n,:K]^T  (+bias), fp32 accum
// 2-stage cp.async pipeline, 128x128x64 tiles, 8 warps, warp tile 64x32.
// ---------------------------------------------------------------------------
static constexpr int LDH = 72;                         // 64 + 8 halves row pad
static constexpr int STAGE_HALFS = 2 * 128 * LDH;      // A + B per stage
static constexpr int SMEM_BYTES = 2 * STAGE_HALFS * 2; // 73728

template <int BIAS>
__global__ void __launch_bounds__(256, 2)
gemm_f16(const __half* __restrict__ A, long lda,
         const __half* __restrict__ Bm, long ldb,
         float* __restrict__ C, long ldc,
         const float* __restrict__ bias, int ktiles) {
    extern __shared__ __align__(16) __half smem[];

    const int tid  = threadIdx.x;
    const int wid  = tid >> 5;
    const int lane = tid & 31;
    const int wm   = wid >> 2;        // 0..1  (64-row half)
    const int wn   = wid & 3;         // 0..3  (32-col quarter)
    const int g    = lane >> 2;       // 0..7
    const int t4   = lane & 3;        // 0..3
    const int m0   = blockIdx.x * 128;
    const int n0   = blockIdx.y * 128;

    const uint32_t sbase = smem_u32(smem);
    const __half* Ab = A + (long)m0 * lda;
    const __half* Bb = Bm + (long)n0 * ldb;

    auto load_stage = [&](int kt, int stg) {
        const uint32_t sa = sbase + (uint32_t)(stg * STAGE_HALFS) * 2;
        const uint32_t sb = sa + 128 * LDH * 2;
        const __half* Asrc = Ab + (long)kt * 64;
        const __half* Bsrc = Bb + (long)kt * 64;
#pragma unroll
        for (int c = 0; c < 4; c++) {
            int idx = c * 256 + tid;
            int row = idx >> 3, q = idx & 7;           // 8 x 16B chunks per row
            CP_ASYNC16(sa + (uint32_t)(row * LDH + q * 8) * 2,
                       Asrc + (long)row * lda + q * 8);
            CP_ASYNC16(sb + (uint32_t)(row * LDH + q * 8) * 2,
                       Bsrc + (long)row * ldb + q * 8);
        }
        CP_COMMIT();
    };

    float acc[4][4][4];
#pragma unroll
    for (int i = 0; i < 4; i++)
#pragma unroll
        for (int j = 0; j < 4; j++)
#pragma unroll
            for (int r = 0; r < 4; r++) acc[i][j][r] = 0.f;

    load_stage(0, 0);

    for (int kt = 0; kt < ktiles; kt++) {
        if (kt + 1 < ktiles) load_stage(kt + 1, (kt + 1) & 1);
        else CP_COMMIT();
        CP_WAIT1();
        __syncthreads();

        const int stg = kt & 1;
        const uint32_t* sAu = (const uint32_t*)(smem + stg * STAGE_HALFS);
        const uint32_t* sBu = sAu + 128 * LDH / 2;     // u32 units

#pragma unroll
        for (int ks = 0; ks < 4; ks++) {               // four k16 steps
            const int ko = ks * 8 + t4;                // u32 offset within row
            uint32_t a[4][4];
#pragma unroll
            for (int i = 0; i < 4; i++) {
                int m = wm * 64 + i * 16 + g;
                a[i][0] = sAu[m * (LDH / 2) + ko];
                a[i][1] = sAu[(m + 8) * (LDH / 2) + ko];
                a[i][2] = sAu[m * (LDH / 2) + ko + 4];
                a[i][3] = sAu[(m + 8) * (LDH / 2) + ko + 4];
            }
            uint32_t b[4][2];
#pragma unroll
            for (int j = 0; j < 4; j++) {
                int n = wn * 32 + j * 8 + g;
                b[j][0] = sBu[n * (LDH / 2) + ko];
                b[j][1] = sBu[n * (LDH / 2) + ko + 4];
            }
#pragma unroll
            for (int i = 0; i < 4; i++)
#pragma unroll
                for (int j = 0; j < 4; j++)
                    MMA_F16(acc[i][j], a[i], b[j]);
        }
        __syncthreads();
    }

    // Epilogue (d0,d1 = row g cols 2t4,2t4+1; d2,d3 = row g+8)
#pragma unroll
    for (int i = 0; i < 4; i++) {
        int row0 = m0 + wm * 64 + i * 16 + g;
#pragma unroll
        for (int j = 0; j < 4; j++) {
            int col = n0 + wn * 32 + j * 8 + 2 * t4;
            float bx = 0.f, by = 0.f;
            if (BIAS) { bx = bias[col]; by = bias[col + 1]; }
            float2 v0 = { acc[i][j][0] + bx, acc[i][j][1] + by };
            float2 v1 = { acc[i][j][2] + bx, acc[i][j][3] + by };
            *(float2*)(C + (long)row0 * ldc + col)       = v0;
            *(float2*)(C + (long)(row0 + 8) * ldc + col) = v1;
        }
    }
}

// ---------------------------------------------------------------------------
// Launch
// ---------------------------------------------------------------------------
extern "C" void kernel_launch(void* const* d_in, const int* in_sizes, int n_in,
                              void* d_out, int out_size) {
    const float* x    = (const float*)d_in[0];
    const float* Wg   = (const float*)d_in[1];
    const float* A    = (const float*)d_in[2];
    const float* B    = (const float*)d_in[3];
    const float* Wb   = (const float*)d_in[4];
    const float* bias = (const float*)d_in[5];
    float* out = (float*)d_out;

    static bool attr_done = false;
    if (!attr_done) {
        cudaFuncSetAttribute(gemm_f16<0>, cudaFuncAttributeMaxDynamicSharedMemorySize, SMEM_BYTES);
        cudaFuncSetAttribute(gemm_f16<1>, cudaFuncAttributeMaxDynamicSharedMemorySize, SMEM_BYTES);
        attr_done = true;
    }

    // 1) fp16 operand staging
    prep_x_kernel<<<(NTOK * DM + 255) / 256, 256>>>(x);
    prep_w_kernel<<<(DM * DM + 255) / 256, 256>>>(Wb);
    prep_b_kernel<<<(128 * DM + 255) / 256, 256>>>(B);
    prep_a_kernel<<<(128 * DM + 255) / 256, 256>>>(A);

    __half *xh, *wh, *ah;
    float* hall;
    cudaGetSymbolAddress((void**)&xh, g_xh);
    cudaGetSymbolAddress((void**)&wh, g_wh);
    cudaGetSymbolAddress((void**)&ah, g_ah);
    cudaGetSymbolAddress((void**)&hall, g_hall);

    // 2) h = x @ A  for all experts  (8192 x 128 x 1024)
    gemm_f16<0><<<dim3(NTOK / 128, 1), 256, SMEM_BYTES>>>(
        xh, KC, ah, DM, hall, 128, nullptr, DM / 64);

    // 3) gating + combine coefficients into g_xh tail columns
    gate_c_kernel<<<(NTOK * 32) / 256, 256>>>(x, Wg);

    // 4) fused output GEMM: out = [x|c] @ [W|Bt]^T + bias  (8192 x 1024 x 1152)
    gemm_f16<1><<<dim3(NTOK / 128, DM / 128), 256, SMEM_BYTES>>>(
        xh, KC, wh, KC, out, DM, bias, KC / 64);
}